// round 5
// baseline (speedup 1.0000x reference)
#include <cuda_runtime.h>
#include <math.h>
#include <stdint.h>

#define TOKENS 2048
#define HDIM   2048
#define H2DIM  1024
#define NE     16
#define NMOD   4
#define CAP    768
#define KD     2048

static constexpr long long C_OFF   = (long long)TOKENS * NE * CAP;
static constexpr long long RP_OFF  = 2 * C_OFF;
static constexpr long long AUX_OFF = RP_OFF + (long long)TOKENS * NE;

// ---------------- device scratch --------------------------------------------
__device__ float g_T1[TOKENS * HDIM];
__device__ float g_T2[TOKENS * HDIM];
__device__ float g_S1[TOKENS * H2DIM];
__device__ float g_glog[TOKENS * NE];
__device__ float g_slog[NMOD * TOKENS * NE];
__device__ float g_partial[8 * NE];
// tf32 split planes
__device__ float g_HSh[TOKENS * HDIM];
__device__ float g_HSl[TOKENS * HDIM];
__device__ float g_ACTh[TOKENS * HDIM];
__device__ float g_ACTl[TOKENS * HDIM];
__device__ float g_Wh[HDIM * HDIM];
__device__ float g_Wl[HDIM * HDIM];

// ---------------- helpers ---------------------------------------------------
__device__ __forceinline__ void split2(float v, uint32_t& hb, uint32_t& lb) {
    asm("cvt.rna.tf32.f32 %0, %1;" : "=r"(hb) : "f"(v));
    float lo = v - __uint_as_float(hb);
    asm("cvt.rna.tf32.f32 %0, %1;" : "=r"(lb) : "f"(lo));
}

__device__ __forceinline__ void mma_tf32(float* c, const uint32_t* a, const uint32_t* b) {
    asm volatile(
        "mma.sync.aligned.m16n8k8.row.col.f32.tf32.tf32.f32 "
        "{%0,%1,%2,%3}, {%4,%5,%6,%7}, {%8,%9}, {%0,%1,%2,%3};"
        : "+f"(c[0]), "+f"(c[1]), "+f"(c[2]), "+f"(c[3])
        : "r"(a[0]), "r"(a[1]), "r"(a[2]), "r"(a[3]), "r"(b[0]), "r"(b[1]));
}

#define CP_ASYNC16(dst, src) \
    asm volatile("cp.async.cg.shared.global [%0], [%1], 16;" :: "r"(dst), "l"(src))
#define CP_COMMIT() asm volatile("cp.async.commit_group;" ::: "memory")
#define CP_WAIT2()  asm volatile("cp.async.wait_group 2;" ::: "memory")

// ---------------- zero-fill --------------------------------------------------
__global__ void zero_kernel(float4* __restrict__ p, int n4) {
    int i = blockIdx.x * blockDim.x + threadIdx.x;
    int stride = gridDim.x * blockDim.x;
    float4 z = make_float4(0.f, 0.f, 0.f, 0.f);
    for (; i < n4; i += stride) p[i] = z;
}

// ---------------- split: fp32 -> tf32 hi/lo planes ---------------------------
__global__ void split_kernel(const float4* __restrict__ src,
                             float4* __restrict__ hi, float4* __restrict__ lo, int n4) {
    int i = blockIdx.x * blockDim.x + threadIdx.x;
    int stride = gridDim.x * blockDim.x;
    for (; i < n4; i += stride) {
        float4 v = src[i];
        uint4 h, l;
        split2(v.x, h.x, l.x); split2(v.y, h.y, l.y);
        split2(v.z, h.z, l.z); split2(v.w, h.w, l.w);
        hi[i] = *(float4*)&h;
        lo[i] = *(float4*)&l;
    }
}

// ---------------- HMMA 3xTF32 GEMM with cp.async 4-stage pipeline ------------
// C[M,N] = act(A[M,2048] @ W[2048,N] + bias). 128x128 CTA tile, BK=16,
// 256 threads, 8 warps with 64x32 warp tiles. Operands pre-split to tf32 hi/lo.
// Stage layout (uint32 words): AH[128][20]=2560, AL=2560, BH[16][136]=2176, BL=2176.
#define AL_W   2560
#define BH_W   5120
#define BL_W   7296
#define STG_W  9472
#define STG_B  (STG_W * 4)
#define NSTG   4
#define SMEM_BYTES (NSTG * STG_B)   // 151552

__global__ __launch_bounds__(256) void gemm_split(
    const float* __restrict__ Ahg, const float* __restrict__ Alg,
    const float* __restrict__ Bhg, const float* __restrict__ Blg,
    const float* __restrict__ bias, float* __restrict__ C,
    int N, int do_relu)
{
    extern __shared__ uint32_t sm[];
    const int tid  = threadIdx.x;
    const int wid  = tid >> 5;
    const int lane = tid & 31;
    const int gid  = lane >> 2;
    const int tig  = lane & 3;
    const int wm   = (wid & 1) * 64;
    const int wn   = (wid >> 1) * 32;
    const int bm   = blockIdx.y * 128;
    const int bn   = blockIdx.x * 128;

    // cp.async per-thread mapping
    const int arow = tid >> 2;           // 0..63 ; second copy +64
    const int aseg = (tid & 3) * 4;      // 0,4,8,12
    const int bkr  = tid >> 5;           // 0..7 ; second copy +8
    const int bcol = (tid & 31) * 4;     // 0..124

    const float* aH0 = Ahg + (size_t)(bm + arow) * KD + aseg;
    const float* aH1 = aH0 + (size_t)64 * KD;
    const float* aL0 = Alg + (size_t)(bm + arow) * KD + aseg;
    const float* aL1 = aL0 + (size_t)64 * KD;
    const float* bH0 = Bhg + (size_t)bkr * N + bn + bcol;
    const float* bH1 = bH0 + (size_t)8 * N;
    const float* bL0 = Blg + (size_t)bkr * N + bn + bcol;
    const float* bL1 = bL0 + (size_t)8 * N;

    const uint32_t smbase = (uint32_t)__cvta_generic_to_shared(sm);
    const uint32_t dA0 = (uint32_t)(arow * 20 + aseg) * 4;
    const uint32_t dA1 = (uint32_t)((arow + 64) * 20 + aseg) * 4;
    const uint32_t dB0 = (uint32_t)(BH_W + bkr * 136 + bcol) * 4;
    const uint32_t dB1 = (uint32_t)(BH_W + (bkr + 8) * 136 + bcol) * 4;

    float acc[4][4][4];
#pragma unroll
    for (int mt = 0; mt < 4; mt++)
#pragma unroll
        for (int nt = 0; nt < 4; nt++)
#pragma unroll
            for (int r = 0; r < 4; r++) acc[mt][nt][r] = 0.f;

    const int KT = KD / 16;   // 128

#define ISSUE_STAGE(s, kb) do {                                   \
    uint32_t sb = smbase + (uint32_t)(s) * STG_B;                 \
    size_t ka = (size_t)(kb) * 16;                                \
    size_t kw = (size_t)(kb) * 16 * N;                            \
    CP_ASYNC16(sb + dA0,            aH0 + ka);                    \
    CP_ASYNC16(sb + dA1,            aH1 + ka);                    \
    CP_ASYNC16(sb + dA0 + AL_W * 4, aL0 + ka);                    \
    CP_ASYNC16(sb + dA1 + AL_W * 4, aL1 + ka);                    \
    CP_ASYNC16(sb + dB0,            bH0 + kw);                    \
    CP_ASYNC16(sb + dB1,            bH1 + kw);                    \
    CP_ASYNC16(sb + dB0 + 2176 * 4, bL0 + kw);                    \
    CP_ASYNC16(sb + dB1 + 2176 * 4, bL1 + kw);                    \
} while (0)

    // prologue: stages 0..2
    ISSUE_STAGE(0, 0); CP_COMMIT();
    ISSUE_STAGE(1, 1); CP_COMMIT();
    ISSUE_STAGE(2, 2); CP_COMMIT();

    for (int kb = 0; kb < KT; kb++) {
        CP_WAIT2();
        __syncthreads();

        const uint32_t* st = sm + (kb & 3) * STG_W;
        const uint32_t* AH = st;
        const uint32_t* ALo = st + AL_W;
        const uint32_t* BH = st + BH_W;
        const uint32_t* BLo = st + BL_W;

#pragma unroll
        for (int k0 = 0; k0 < 16; k0 += 8) {
            uint32_t fa[4][4], fa2[4][4], fb[4][2];
#pragma unroll
            for (int mt = 0; mt < 4; mt++) {
                int rbase = (wm + mt * 16 + gid) * 20 + k0 + tig;
                fa[mt][0] = AH[rbase];
                fa[mt][1] = AH[rbase + 8 * 20];
                fa[mt][2] = AH[rbase + 4];
                fa[mt][3] = AH[rbase + 8 * 20 + 4];
            }
#pragma unroll
            for (int nt = 0; nt < 4; nt++) {
                int cbase = (k0 + tig) * 136 + wn + nt * 8 + gid;
                fb[nt][0] = BH[cbase];
                fb[nt][1] = BH[cbase + 4 * 136];
            }
#pragma unroll
            for (int mt = 0; mt < 4; mt++)
#pragma unroll
                for (int nt = 0; nt < 4; nt++)
                    mma_tf32(acc[mt][nt], fa[mt], fb[nt]);
#pragma unroll
            for (int mt = 0; mt < 4; mt++) {
                int rbase = (wm + mt * 16 + gid) * 20 + k0 + tig;
                fa2[mt][0] = ALo[rbase];
                fa2[mt][1] = ALo[rbase + 8 * 20];
                fa2[mt][2] = ALo[rbase + 4];
                fa2[mt][3] = ALo[rbase + 8 * 20 + 4];
            }
#pragma unroll
            for (int mt = 0; mt < 4; mt++)
#pragma unroll
                for (int nt = 0; nt < 4; nt++)
                    mma_tf32(acc[mt][nt], fa2[mt], fb[nt]);
#pragma unroll
            for (int nt = 0; nt < 4; nt++) {
                int cbase = (k0 + tig) * 136 + wn + nt * 8 + gid;
                fb[nt][0] = BLo[cbase];
                fb[nt][1] = BLo[cbase + 4 * 136];
            }
#pragma unroll
            for (int mt = 0; mt < 4; mt++)
#pragma unroll
                for (int nt = 0; nt < 4; nt++)
                    mma_tf32(acc[mt][nt], fa[mt], fb[nt]);
        }

        if (kb + 3 < KT) ISSUE_STAGE((kb + 3) & 3, kb + 3);
        CP_COMMIT();
    }

    // ---- epilogue ----
#pragma unroll
    for (int nt = 0; nt < 4; nt++) {
        int col = bn + wn + nt * 8 + 2 * tig;
        float b0 = bias[col], b1 = bias[col + 1];
#pragma unroll
        for (int mt = 0; mt < 4; mt++) {
            int row = bm + wm + mt * 16 + gid;
            float v0 = acc[mt][nt][0] + b0;
            float v1 = acc[mt][nt][1] + b1;
            float v2 = acc[mt][nt][2] + b0;
            float v3 = acc[mt][nt][3] + b1;
            if (do_relu) {
                v0 = fmaxf(v0, 0.f); v1 = fmaxf(v1, 0.f);
                v2 = fmaxf(v2, 0.f); v3 = fmaxf(v3, 0.f);
            }
            *(float2*)(C + (size_t)row * N + col)       = make_float2(v0, v1);
            *(float2*)(C + (size_t)(row + 8) * N + col) = make_float2(v2, v3);
        }
    }
}

// ---------------- logits: warp-per-token, out[T,16] = X @ W + bias -----------
__global__ __launch_bounds__(128) void logits_kernel(
    const float* __restrict__ X, const float* __restrict__ W,
    const float* __restrict__ bias, float* __restrict__ out, int Kd)
{
    __shared__ float wt[NE][257];
    const int tid = threadIdx.x;
    const int wid = tid >> 5;
    const int lane = tid & 31;
    const int tok = blockIdx.x * 4 + wid;

    float acc[NE];
#pragma unroll
    for (int e = 0; e < NE; e++) acc[e] = 0.f;

    const float* xrow = X + (size_t)tok * Kd;

    for (int c = 0; c < Kd; c += 256) {
#pragma unroll
        for (int l = 0; l < 8; l++) {
            int id = tid + l * 128;
            int k  = id >> 2;
            int e4 = (id & 3) << 2;
            float4 v = *(const float4*)(W + (size_t)(c + k) * NE + e4);
            wt[e4 + 0][k] = v.x;
            wt[e4 + 1][k] = v.y;
            wt[e4 + 2][k] = v.z;
            wt[e4 + 3][k] = v.w;
        }
        __syncthreads();
#pragma unroll
        for (int i = 0; i < 8; i++) {
            int kk = i * 32 + lane;
            float xv = xrow[c + kk];
#pragma unroll
            for (int e = 0; e < NE; e++)
                acc[e] = fmaf(xv, wt[e][kk], acc[e]);
        }
        __syncthreads();
    }
#pragma unroll
    for (int off = 16; off > 0; off >>= 1)
#pragma unroll
        for (int e = 0; e < NE; e++)
            acc[e] += __shfl_xor_sync(0xffffffffu, acc[e], off);
    if (lane == 0) {
#pragma unroll
        for (int e = 0; e < NE; e++)
            out[(size_t)tok * NE + e] = acc[e] + bias[e];
    }
}

// ---------------- router ------------------------------------------------------
__global__ __launch_bounds__(256) void router_kernel(
    const float* __restrict__ glog, const float* __restrict__ slog,
    float* __restrict__ out, float* __restrict__ partial)
{
    __shared__ float sh[256][NE];
    const int tid = threadIdx.x;
    const int tok = blockIdx.x * 256 + tid;

    float probs[NE];
    {
        float g[NE];
#pragma unroll
        for (int i = 0; i < NE; i++) g[i] = glog[(size_t)tok * NE + i];
        float mx = g[0];
#pragma unroll
        for (int i = 1; i < NE; i++) mx = fmaxf(mx, g[i]);
        float s = 0.f;
#pragma unroll
        for (int i = 0; i < NE; i++) { g[i] = expf(g[i] - mx); s += g[i]; }
        float inv = 0.7f / s;
#pragma unroll
        for (int i = 0; i < NE; i++) probs[i] = g[i] * inv;
    }
#pragma unroll
    for (int m = 0; m < NMOD; m++) {
        float g[NE];
#pragma unroll
        for (int i = 0; i < NE; i++)
            g[i] = slog[((size_t)m * TOKENS + tok) * NE + i];
        float mx = g[0];
#pragma unroll
        for (int i = 1; i < NE; i++) mx = fmaxf(mx, g[i]);
        float s = 0.f;
#pragma unroll
        for (int i = 0; i < NE; i++) { g[i] = expf(g[i] - mx); s += g[i]; }
        float inv = 0.15f / s;
#pragma unroll
        for (int i = 0; i < NE; i++) probs[i] += g[i] * inv;
    }

#pragma unroll
    for (int i = 0; i < NE; i++)
        out[RP_OFF + (size_t)tok * NE + i] = probs[i];

    unsigned used = 0;
    int idx[4]; float val[4]; float vsum = 0.f;
#pragma unroll
    for (int k = 0; k < 4; k++) {
        float best = -1.f; int bi = 0;
#pragma unroll
        for (int i = 0; i < NE; i++) {
            bool ok = !((used >> i) & 1u);
            if (ok && probs[i] > best) { best = probs[i]; bi = i; }
        }
        used |= (1u << bi);
        idx[k] = bi; val[k] = best; vsum += best;
    }
    float invv = 1.f / vsum;
#pragma unroll
    for (int k = 0; k < 4; k++) {
        size_t base = ((size_t)tok * NE + idx[k]) * CAP;
        out[base]         = 1.f;
        out[C_OFF + base] = val[k] * invv;
    }

#pragma unroll
    for (int i = 0; i < NE; i++) sh[tid][i] = probs[i];
    __syncthreads();
    if (tid < NE) {
        float s = 0.f;
        for (int i = 0; i < 256; i++) s += sh[i][tid];
        partial[blockIdx.x * NE + tid] = s;
    }
}

// ---------------- aux loss ----------------------------------------------------
__global__ void aux_kernel(const float* __restrict__ partial, float* __restrict__ out)
{
    const int tid = threadIdx.x;
    float v = 0.f;
    if (tid < NE) {
        float s = 0.f;
#pragma unroll
        for (int b = 0; b < 8; b++) s += partial[b * NE + tid];
        float mp = s * (1.f / (float)TOKENS);
        v = mp * logf(mp * (float)NE + 1e-9f);
    }
#pragma unroll
    for (int off = 16; off > 0; off >>= 1)
        v += __shfl_down_sync(0xffffffffu, v, off);
    if (tid == 0) out[AUX_OFF] = v;
}

// ---------------- launch ------------------------------------------------------
extern "C" void kernel_launch(void* const* d_in, const int* in_sizes, int n_in,
                              void* d_out, int out_size)
{
    const float* hs   = (const float*)d_in[0];
    const float* mimg = (const float*)d_in[1];
    const float* mgen = (const float*)d_in[2];
    const float* Wg1  = (const float*)d_in[3];
    const float* bg1  = (const float*)d_in[4];
    const float* Wg2  = (const float*)d_in[5];
    const float* bg2  = (const float*)d_in[6];
    const float* Wm1  = (const float*)d_in[7];
    const float* bm1  = (const float*)d_in[8];
    const float* Wm2  = (const float*)d_in[9];
    const float* bm2  = (const float*)d_in[10];
    const float* Ws1  = (const float*)d_in[11];
    const float* bs1  = (const float*)d_in[12];
    const float* Ws2  = (const float*)d_in[13];
    const float* bs2  = (const float*)d_in[14];
    float* out = (float*)d_out;

    float *T1, *T2, *S1, *glog, *slog, *partial;
    float *HSh, *HSl, *ACTh, *ACTl, *Wh, *Wl;
    cudaGetSymbolAddress((void**)&T1,      g_T1);
    cudaGetSymbolAddress((void**)&T2,      g_T2);
    cudaGetSymbolAddress((void**)&S1,      g_S1);
    cudaGetSymbolAddress((void**)&glog,    g_glog);
    cudaGetSymbolAddress((void**)&slog,    g_slog);
    cudaGetSymbolAddress((void**)&partial, g_partial);
    cudaGetSymbolAddress((void**)&HSh,     g_HSh);
    cudaGetSymbolAddress((void**)&HSl,     g_HSl);
    cudaGetSymbolAddress((void**)&ACTh,    g_ACTh);
    cudaGetSymbolAddress((void**)&ACTl,    g_ACTl);
    cudaGetSymbolAddress((void**)&Wh,      g_Wh);
    cudaGetSymbolAddress((void**)&Wl,      g_Wl);

    cudaFuncSetAttribute(gemm_split,
                         cudaFuncAttributeMaxDynamicSharedMemorySize, SMEM_BYTES);

    zero_kernel<<<4096, 256>>>((float4*)out, (int)(2 * C_OFF / 4));

    const int n4_big = TOKENS * HDIM / 4;      // 1M float4
    const int n4_mid = HDIM * H2DIM / 4;       // 512K float4

    dim3 gbig(16, 16);   // N=2048
    dim3 gmid(8, 16);    // N=1024

    // hs split (used by GEMM1 and GEMM3)
    split_kernel<<<2048, 256>>>((const float4*)hs, (float4*)HSh, (float4*)HSl, n4_big);

    // missing-modality encoder: T1 = relu(hs@Wm1+bm1); T2 = T1@Wm2+bm2
    split_kernel<<<2048, 256>>>((const float4*)Wm1, (float4*)Wh, (float4*)Wl, n4_big);
    gemm_split<<<gbig, 256, SMEM_BYTES>>>(HSh, HSl, Wh, Wl, bm1, T1, HDIM, 1);
    split_kernel<<<2048, 256>>>((const float4*)T1, (float4*)ACTh, (float4*)ACTl, n4_big);
    split_kernel<<<2048, 256>>>((const float4*)Wm2, (float4*)Wh, (float4*)Wl, n4_big);
    gemm_split<<<gbig, 256, SMEM_BYTES>>>(ACTh, ACTl, Wh, Wl, bm2, T2, HDIM, 0);

    // generalized router: T1 = relu(hs@Wg1+bg1); glog = T1@Wg2+bg2
    split_kernel<<<2048, 256>>>((const float4*)Wg1, (float4*)Wh, (float4*)Wl, n4_big);
    gemm_split<<<gbig, 256, SMEM_BYTES>>>(HSh, HSl, Wh, Wl, bg1, T1, HDIM, 1);
    logits_kernel<<<512, 128>>>(T1, Wg2, bg2, glog, HDIM);

    // specialized routers
    for (int m = 0; m < NMOD; m++) {
        const float* data = (m == 0) ? mimg : (m == 1) ? mgen : T2;
        if (m < 3)  // m==3 reuses T2 split from m==2
            split_kernel<<<2048, 256>>>((const float4*)data, (float4*)ACTh, (float4*)ACTl, n4_big);
        split_kernel<<<2048, 256>>>((const float4*)(Ws1 + (size_t)m * HDIM * H2DIM),
                                    (float4*)Wh, (float4*)Wl, n4_mid);
        gemm_split<<<gmid, 256, SMEM_BYTES>>>(ACTh, ACTl, Wh, Wl,
                                              bs1 + (size_t)m * H2DIM, S1, H2DIM, 1);
        logits_kernel<<<512, 128>>>(S1, Ws2 + (size_t)m * H2DIM * NE,
                                    bs2 + (size_t)m * NE,
                                    slog + (size_t)m * TOKENS * NE, H2DIM);
    }

    router_kernel<<<8, 256>>>(glog, slog, out, partial);
    aux_kernel<<<1, 32>>>(partial, out);
}

// round 6
// speedup vs baseline: 1.5957x; 1.5957x over previous
#include <cuda_runtime.h>
#include <math.h>
#include <stdint.h>

#define TOKENS 2048
#define HDIM   2048
#define H2DIM  1024
#define NE     16
#define NMOD   4
#define CAP    768
#define KD     2048

static constexpr long long C_OFF   = (long long)TOKENS * NE * CAP;
static constexpr long long RP_OFF  = 2 * C_OFF;
static constexpr long long AUX_OFF = RP_OFF + (long long)TOKENS * NE;

// ---------------- device scratch ---------------------------------------------
__device__ float g_T1 [TOKENS * HDIM];          // relu(hs@Wm1+bm1)
__device__ float g_T1g[TOKENS * HDIM];          // relu(hs@Wg1+bg1)
__device__ float g_T2 [TOKENS * HDIM];          // missing_rep
__device__ float g_S1 [NMOD * TOKENS * H2DIM];  // per-modality hidden
__device__ float g_glog[TOKENS * NE];
__device__ float g_slog[NMOD * TOKENS * NE];
__device__ float g_partial[8 * NE];

struct GemmBatch {
    const float* A[4];
    const float* B[4];
    const float* bias[4];
    float*       C[4];
};

// ---------------- helpers ------------------------------------------------------
__device__ __forceinline__ void split2(float v, uint32_t& hb, uint32_t& lb) {
    asm("cvt.rna.tf32.f32 %0, %1;" : "=r"(hb) : "f"(v));
    float lo = v - __uint_as_float(hb);
    asm("cvt.rna.tf32.f32 %0, %1;" : "=r"(lb) : "f"(lo));
}

__device__ __forceinline__ void mma_tf32(float* c, const uint32_t* a, const uint32_t* b) {
    asm volatile(
        "mma.sync.aligned.m16n8k8.row.col.f32.tf32.tf32.f32 "
        "{%0,%1,%2,%3}, {%4,%5,%6,%7}, {%8,%9}, {%0,%1,%2,%3};"
        : "+f"(c[0]), "+f"(c[1]), "+f"(c[2]), "+f"(c[3])
        : "r"(a[0]), "r"(a[1]), "r"(a[2]), "r"(a[3]), "r"(b[0]), "r"(b[1]));
}

// ---------------- zero-fill -----------------------------------------------------
__global__ void zero_kernel(float4* __restrict__ p, int n4) {
    int i = blockIdx.x * blockDim.x + threadIdx.x;
    int stride = gridDim.x * blockDim.x;
    float4 z = make_float4(0.f, 0.f, 0.f, 0.f);
    for (; i < n4; i += stride) p[i] = z;
}

// ---------------- HMMA 3xTF32 GEMM, double-buffered smem, z-batched ------------
// C[M,N] = act(A[M,2048] @ W[2048,N] + bias). 128x128 CTA tile, BK=32,
// 256 threads (8 warps, 64x32 warp tiles). In-kernel tf32 hi/lo split.
// Per-stage smem (uint32 words): Ah[128][40]=5120, Al=5120, Bh[32][136]=4352, Bl=4352.
#define STG_W  18944
#define SMEM_BYTES (2 * STG_W * 4)   // 151552

__global__ __launch_bounds__(256) void gemm_hmma_b(
    GemmBatch gb, int N, int do_relu)
{
    extern __shared__ uint32_t sm[];

    const int z    = blockIdx.z;
    const float* __restrict__ A    = gb.A[z];
    const float* __restrict__ W    = gb.B[z];
    const float* __restrict__ bias = gb.bias[z];
    float* __restrict__ C          = gb.C[z];

    const int tid  = threadIdx.x;
    const int wid  = tid >> 5;
    const int lane = tid & 31;
    const int gid  = lane >> 2;
    const int tig  = lane & 3;
    const int wm   = (wid & 1) * 64;
    const int wn   = (wid >> 1) * 32;
    const int bm   = blockIdx.y * 128;
    const int bn   = blockIdx.x * 128;

    // global load mapping
    const int arow0 = tid >> 3;          // + 32*l
    const int aseg  = (tid & 7) * 4;     // k offset within BK
    const int bkr0  = tid >> 5;          // + 8*l
    const int bcol  = (tid & 31) * 4;    // n offset within 128

    float acc[4][4][4];
#pragma unroll
    for (int mt = 0; mt < 4; mt++)
#pragma unroll
        for (int nt = 0; nt < 4; nt++)
#pragma unroll
            for (int r = 0; r < 4; r++) acc[mt][nt][r] = 0.f;

    float4 av[4], bv[4];
#pragma unroll
    for (int l = 0; l < 4; l++)
        av[l] = *(const float4*)(A + (size_t)(bm + arow0 + 32 * l) * KD + aseg);
#pragma unroll
    for (int l = 0; l < 4; l++)
        bv[l] = *(const float4*)(W + (size_t)(bkr0 + 8 * l) * N + bn + bcol);

    for (int kb = 0; kb < KD / 32; kb++) {
        uint32_t* st = sm + (kb & 1) * STG_W;
        uint32_t* Ah = st;
        uint32_t* Al = st + 5120;
        uint32_t* Bh = st + 10240;
        uint32_t* Bl = st + 14592;

        // ---- split + store current tile ----
#pragma unroll
        for (int l = 0; l < 4; l++) {
            uint4 h, lo;
            split2(av[l].x, h.x, lo.x); split2(av[l].y, h.y, lo.y);
            split2(av[l].z, h.z, lo.z); split2(av[l].w, h.w, lo.w);
            int off = (arow0 + 32 * l) * 40 + aseg;
            *(uint4*)(Ah + off) = h;
            *(uint4*)(Al + off) = lo;
        }
#pragma unroll
        for (int l = 0; l < 4; l++) {
            uint4 h, lo;
            split2(bv[l].x, h.x, lo.x); split2(bv[l].y, h.y, lo.y);
            split2(bv[l].z, h.z, lo.z); split2(bv[l].w, h.w, lo.w);
            int off = (bkr0 + 8 * l) * 136 + bcol;
            *(uint4*)(Bh + off) = h;
            *(uint4*)(Bl + off) = lo;
        }
        __syncthreads();   // single barrier per iteration (double buffer)

        // ---- prefetch next tile (latency hidden under MMA phase) ----
        if (kb + 1 < KD / 32) {
            const float* Ap = A + (size_t)bm * KD + (kb + 1) * 32;
            const float* Wp = W + (size_t)(kb + 1) * 32 * N + bn;
#pragma unroll
            for (int l = 0; l < 4; l++)
                av[l] = *(const float4*)(Ap + (size_t)(arow0 + 32 * l) * KD + aseg);
#pragma unroll
            for (int l = 0; l < 4; l++)
                bv[l] = *(const float4*)(Wp + (size_t)(bkr0 + 8 * l) * N + bcol);
        }

        // ---- MMA phase: 4 k8-steps, 3-pass tf32 split ----
#pragma unroll
        for (int k0 = 0; k0 < 32; k0 += 8) {
            uint32_t fa[4][4], fa2[4][4], fb[4][2];
#pragma unroll
            for (int mt = 0; mt < 4; mt++) {
                int rbase = (wm + mt * 16 + gid) * 40 + k0 + tig;
                fa[mt][0] = Ah[rbase];
                fa[mt][1] = Ah[rbase + 8 * 40];
                fa[mt][2] = Ah[rbase + 4];
                fa[mt][3] = Ah[rbase + 8 * 40 + 4];
            }
#pragma unroll
            for (int nt = 0; nt < 4; nt++) {
                int cbase = (k0 + tig) * 136 + wn + nt * 8 + gid;
                fb[nt][0] = Bh[cbase];
                fb[nt][1] = Bh[cbase + 4 * 136];
            }
#pragma unroll
            for (int mt = 0; mt < 4; mt++)
#pragma unroll
                for (int nt = 0; nt < 4; nt++)
                    mma_tf32(acc[mt][nt], fa[mt], fb[nt]);
#pragma unroll
            for (int mt = 0; mt < 4; mt++) {
                int rbase = (wm + mt * 16 + gid) * 40 + k0 + tig;
                fa2[mt][0] = Al[rbase];
                fa2[mt][1] = Al[rbase + 8 * 40];
                fa2[mt][2] = Al[rbase + 4];
                fa2[mt][3] = Al[rbase + 8 * 40 + 4];
            }
#pragma unroll
            for (int mt = 0; mt < 4; mt++)
#pragma unroll
                for (int nt = 0; nt < 4; nt++)
                    mma_tf32(acc[mt][nt], fa2[mt], fb[nt]);
#pragma unroll
            for (int nt = 0; nt < 4; nt++) {
                int cbase = (k0 + tig) * 136 + wn + nt * 8 + gid;
                fb[nt][0] = Bl[cbase];
                fb[nt][1] = Bl[cbase + 4 * 136];
            }
#pragma unroll
            for (int mt = 0; mt < 4; mt++)
#pragma unroll
                for (int nt = 0; nt < 4; nt++)
                    mma_tf32(acc[mt][nt], fa[mt], fb[nt]);
        }
        // no trailing barrier: next store targets the other buffer, and the
        // next iteration's barrier orders reads-of-this-buffer vs stores-in-2.
    }

    // ---- epilogue ----
#pragma unroll
    for (int nt = 0; nt < 4; nt++) {
        int col = bn + wn + nt * 8 + 2 * tig;
        float b0 = bias[col], b1 = bias[col + 1];
#pragma unroll
        for (int mt = 0; mt < 4; mt++) {
            int row = bm + wm + mt * 16 + gid;
            float v0 = acc[mt][nt][0] + b0;
            float v1 = acc[mt][nt][1] + b1;
            float v2 = acc[mt][nt][2] + b0;
            float v3 = acc[mt][nt][3] + b1;
            if (do_relu) {
                v0 = fmaxf(v0, 0.f); v1 = fmaxf(v1, 0.f);
                v2 = fmaxf(v2, 0.f); v3 = fmaxf(v3, 0.f);
            }
            *(float2*)(C + (size_t)row * N + col)       = make_float2(v0, v1);
            *(float2*)(C + (size_t)(row + 8) * N + col) = make_float2(v2, v3);
        }
    }
}

// ---------------- logits: warp-per-token, z-batched ---------------------------
struct LogitsBatch {
    const float* X[4];
    const float* W[4];
    const float* bias[4];
    float*       out[4];
};

__global__ __launch_bounds__(128) void logits_b(LogitsBatch lb, int Kd)
{
    __shared__ float wt[NE][257];
    const int z = blockIdx.z;
    const float* __restrict__ X    = lb.X[z];
    const float* __restrict__ W    = lb.W[z];
    const float* __restrict__ bias = lb.bias[z];
    float* __restrict__ out        = lb.out[z];

    const int tid = threadIdx.x;
    const int wid = tid >> 5;
    const int lane = tid & 31;
    const int tok = blockIdx.x * 4 + wid;

    float acc[NE];
#pragma unroll
    for (int e = 0; e < NE; e++) acc[e] = 0.f;

    const float* xrow = X + (size_t)tok * Kd;

    for (int c = 0; c < Kd; c += 256) {
#pragma unroll
        for (int l = 0; l < 8; l++) {
            int id = tid + l * 128;
            int k  = id >> 2;
            int e4 = (id & 3) << 2;
            float4 v = *(const float4*)(W + (size_t)(c + k) * NE + e4);
            wt[e4 + 0][k] = v.x;
            wt[e4 + 1][k] = v.y;
            wt[e4 + 2][k] = v.z;
            wt[e4 + 3][k] = v.w;
        }
        __syncthreads();
#pragma unroll
        for (int i = 0; i < 8; i++) {
            int kk = i * 32 + lane;
            float xv = xrow[c + kk];
#pragma unroll
            for (int e = 0; e < NE; e++)
                acc[e] = fmaf(xv, wt[e][kk], acc[e]);
        }
        __syncthreads();
    }
#pragma unroll
    for (int off = 16; off > 0; off >>= 1)
#pragma unroll
        for (int e = 0; e < NE; e++)
            acc[e] += __shfl_xor_sync(0xffffffffu, acc[e], off);
    if (lane == 0) {
#pragma unroll
        for (int e = 0; e < NE; e++)
            out[(size_t)tok * NE + e] = acc[e] + bias[e];
    }
}

// ---------------- router --------------------------------------------------------
__global__ __launch_bounds__(256) void router_kernel(
    const float* __restrict__ glog, const float* __restrict__ slog,
    float* __restrict__ out, float* __restrict__ partial)
{
    __shared__ float sh[256][NE];
    const int tid = threadIdx.x;
    const int tok = blockIdx.x * 256 + tid;

    float probs[NE];
    {
        float g[NE];
#pragma unroll
        for (int i = 0; i < NE; i++) g[i] = glog[(size_t)tok * NE + i];
        float mx = g[0];
#pragma unroll
        for (int i = 1; i < NE; i++) mx = fmaxf(mx, g[i]);
        float s = 0.f;
#pragma unroll
        for (int i = 0; i < NE; i++) { g[i] = expf(g[i] - mx); s += g[i]; }
        float inv = 0.7f / s;
#pragma unroll
        for (int i = 0; i < NE; i++) probs[i] = g[i] * inv;
    }
#pragma unroll
    for (int m = 0; m < NMOD; m++) {
        float g[NE];
#pragma unroll
        for (int i = 0; i < NE; i++)
            g[i] = slog[((size_t)m * TOKENS + tok) * NE + i];
        float mx = g[0];
#pragma unroll
        for (int i = 1; i < NE; i++) mx = fmaxf(mx, g[i]);
        float s = 0.f;
#pragma unroll
        for (int i = 0; i < NE; i++) { g[i] = expf(g[i] - mx); s += g[i]; }
        float inv = 0.15f / s;
#pragma unroll
        for (int i = 0; i < NE; i++) probs[i] += g[i] * inv;
    }

#pragma unroll
    for (int i = 0; i < NE; i++)
        out[RP_OFF + (size_t)tok * NE + i] = probs[i];

    unsigned used = 0;
    int idx[4]; float val[4]; float vsum = 0.f;
#pragma unroll
    for (int k = 0; k < 4; k++) {
        float best = -1.f; int bi = 0;
#pragma unroll
        for (int i = 0; i < NE; i++) {
            bool ok = !((used >> i) & 1u);
            if (ok && probs[i] > best) { best = probs[i]; bi = i; }
        }
        used |= (1u << bi);
        idx[k] = bi; val[k] = best; vsum += best;
    }
    float invv = 1.f / vsum;
#pragma unroll
    for (int k = 0; k < 4; k++) {
        size_t base = ((size_t)tok * NE + idx[k]) * CAP;
        out[base]         = 1.f;
        out[C_OFF + base] = val[k] * invv;
    }

#pragma unroll
    for (int i = 0; i < NE; i++) sh[tid][i] = probs[i];
    __syncthreads();
    if (tid < NE) {
        float s = 0.f;
        for (int i = 0; i < 256; i++) s += sh[i][tid];
        partial[blockIdx.x * NE + tid] = s;
    }
}

// ---------------- aux loss ------------------------------------------------------
__global__ void aux_kernel(const float* __restrict__ partial, float* __restrict__ out)
{
    const int tid = threadIdx.x;
    float v = 0.f;
    if (tid < NE) {
        float s = 0.f;
#pragma unroll
        for (int b = 0; b < 8; b++) s += partial[b * NE + tid];
        float mp = s * (1.f / (float)TOKENS);
        v = mp * logf(mp * (float)NE + 1e-9f);
    }
#pragma unroll
    for (int off = 16; off > 0; off >>= 1)
        v += __shfl_down_sync(0xffffffffu, v, off);
    if (tid == 0) out[AUX_OFF] = v;
}

// ---------------- launch --------------------------------------------------------
extern "C" void kernel_launch(void* const* d_in, const int* in_sizes, int n_in,
                              void* d_out, int out_size)
{
    const float* hs   = (const float*)d_in[0];
    const float* mimg = (const float*)d_in[1];
    const float* mgen = (const float*)d_in[2];
    const float* Wg1  = (const float*)d_in[3];
    const float* bg1  = (const float*)d_in[4];
    const float* Wg2  = (const float*)d_in[5];
    const float* bg2  = (const float*)d_in[6];
    const float* Wm1  = (const float*)d_in[7];
    const float* bm1  = (const float*)d_in[8];
    const float* Wm2  = (const float*)d_in[9];
    const float* bm2  = (const float*)d_in[10];
    const float* Ws1  = (const float*)d_in[11];
    const float* bs1  = (const float*)d_in[12];
    const float* Ws2  = (const float*)d_in[13];
    const float* bs2  = (const float*)d_in[14];
    float* out = (float*)d_out;

    float *T1, *T1g, *T2, *S1, *glog, *slog, *partial;
    cudaGetSymbolAddress((void**)&T1,      g_T1);
    cudaGetSymbolAddress((void**)&T1g,     g_T1g);
    cudaGetSymbolAddress((void**)&T2,      g_T2);
    cudaGetSymbolAddress((void**)&S1,      g_S1);
    cudaGetSymbolAddress((void**)&glog,    g_glog);
    cudaGetSymbolAddress((void**)&slog,    g_slog);
    cudaGetSymbolAddress((void**)&partial, g_partial);

    cudaFuncSetAttribute(gemm_hmma_b,
                         cudaFuncAttributeMaxDynamicSharedMemorySize, SMEM_BYTES);

    zero_kernel<<<4096, 256>>>((float4*)out, (int)(2 * C_OFF / 4));

    // 1. fused big GEMMs sharing A=hs: z=0 -> T1 (Wm1), z=1 -> T1g (Wg1)
    {
        GemmBatch gb{};
        gb.A[0] = hs;  gb.B[0] = Wm1; gb.bias[0] = bm1; gb.C[0] = T1;
        gb.A[1] = hs;  gb.B[1] = Wg1; gb.bias[1] = bg1; gb.C[1] = T1g;
        dim3 grid(16, 16, 2);
        gemm_hmma_b<<<grid, 256, SMEM_BYTES>>>(gb, HDIM, 1);
    }

    // 2. GEMM2: T2 = T1 @ Wm2 + bm2 (no relu)
    {
        GemmBatch gb{};
        gb.A[0] = T1; gb.B[0] = Wm2; gb.bias[0] = bm2; gb.C[0] = T2;
        dim3 grid(16, 16, 1);
        gemm_hmma_b<<<grid, 256, SMEM_BYTES>>>(gb, HDIM, 0);
    }

    // 3. fused mid GEMMs: S1[m] = relu(data_m @ Ws1_m + bs1_m)
    {
        GemmBatch gb{};
        const float* data[4] = { mimg, mgen, T2, T2 };
        for (int m = 0; m < 4; m++) {
            gb.A[m]    = data[m];
            gb.B[m]    = Ws1 + (size_t)m * HDIM * H2DIM;
            gb.bias[m] = bs1 + (size_t)m * H2DIM;
            gb.C[m]    = S1 + (size_t)m * TOKENS * H2DIM;
        }
        dim3 grid(8, 16, 4);
        gemm_hmma_b<<<grid, 256, SMEM_BYTES>>>(gb, H2DIM, 1);
    }

    // 4. generalized logits
    {
        LogitsBatch lb{};
        lb.X[0] = T1g; lb.W[0] = Wg2; lb.bias[0] = bg2; lb.out[0] = glog;
        dim3 grid(512, 1, 1);
        logits_b<<<grid, 128>>>(lb, HDIM);
    }

    // 5. fused specialized logits
    {
        LogitsBatch lb{};
        for (int m = 0; m < 4; m++) {
            lb.X[m]    = S1 + (size_t)m * TOKENS * H2DIM;
            lb.W[m]    = Ws2 + (size_t)m * H2DIM * NE;
            lb.bias[m] = bs2 + (size_t)m * NE;
            lb.out[m]  = slog + (size_t)m * TOKENS * NE;
        }
        dim3 grid(512, 1, 4);
        logits_b<<<grid, 128>>>(lb, H2DIM);
    }

    router_kernel<<<8, 256>>>(glog, slog, out, partial);
    aux_kernel<<<1, 32>>>(partial, out);
}